// round 1
// baseline (speedup 1.0000x reference)
#include <cuda_runtime.h>
#include <math_constants.h>

#define B_  4
#define L_  4096
#define D_  256
#define BL_ (B_ * L_)

// Scratch for projected+normalized q, k (allocation-free: device globals).
__device__ float g_Q[BL_ * D_];
__device__ float g_K[BL_ * D_];

// ---------------------------------------------------------------------------
// Packed f32x2 FMA (sm_100+): two independent fp32 FMAs per instruction.
// ---------------------------------------------------------------------------
__device__ __forceinline__ unsigned long long fma2(unsigned long long a,
                                                   unsigned long long b,
                                                   unsigned long long c) {
    unsigned long long d;
    asm("fma.rn.f32x2 %0, %1, %2, %3;" : "=l"(d) : "l"(a), "l"(b), "l"(c));
    return d;
}

// ---------------------------------------------------------------------------
// Kernel 1: y[r][c] = sum_d X[r][d] * W[c][d], then L2-normalize each row.
// Block: 128 threads, 32 rows x 256 cols. Thread tile: 8 rows x 8 cols.
// which==0 -> g_Q, which==1 -> g_K.
// ---------------------------------------------------------------------------
__global__ void __launch_bounds__(128)
proj_norm_kernel(const float* __restrict__ X, const float* __restrict__ W,
                 int which) {
    __shared__ __align__(16) float X_s[32][33];
    __shared__ __align__(16) float W_s[256][33];

    float* __restrict__ Out = which ? g_K : g_Q;

    const int tid = threadIdx.x;
    const int rg  = tid >> 5;   // warp id 0..3 -> row group
    const int cg  = tid & 31;   // lane        -> col group
    const int row0 = blockIdx.x * 32;

    float acc[8][8];
#pragma unroll
    for (int i = 0; i < 8; i++)
#pragma unroll
        for (int j = 0; j < 8; j++) acc[i][j] = 0.f;

    for (int d0 = 0; d0 < D_; d0 += 32) {
        // Load X chunk: 32x32 floats = 256 float4; 2 per thread.
#pragma unroll
        for (int t = 0; t < 2; t++) {
            int idx = tid + t * 128;       // float4 index
            int r = idx >> 3;
            int d4 = (idx & 7) * 4;
            float4 v = *(const float4*)&X[(row0 + r) * D_ + d0 + d4];
            X_s[r][d4 + 0] = v.x; X_s[r][d4 + 1] = v.y;
            X_s[r][d4 + 2] = v.z; X_s[r][d4 + 3] = v.w;
        }
        // Load W chunk: 256x32 floats = 2048 float4; 16 per thread.
#pragma unroll
        for (int t = 0; t < 16; t++) {
            int idx = tid + t * 128;
            int c = idx >> 3;
            int d4 = (idx & 7) * 4;
            float4 v = *(const float4*)&W[c * D_ + d0 + d4];
            W_s[c][d4 + 0] = v.x; W_s[c][d4 + 1] = v.y;
            W_s[c][d4 + 2] = v.z; W_s[c][d4 + 3] = v.w;
        }
        __syncthreads();
#pragma unroll 8
        for (int d = 0; d < 32; d++) {
            float w[8], x[8];
#pragma unroll
            for (int cc = 0; cc < 8; cc++) w[cc] = W_s[cc * 32 + cg][d];
#pragma unroll
            for (int ii = 0; ii < 8; ii++) x[ii] = X_s[ii * 4 + rg][d];
#pragma unroll
            for (int ii = 0; ii < 8; ii++)
#pragma unroll
                for (int cc = 0; cc < 8; cc++)
                    acc[ii][cc] = fmaf(x[ii], w[cc], acc[ii][cc]);
        }
        __syncthreads();
    }

    // Row L2 norm: each row lives entirely inside one warp (8 cols/lane).
#pragma unroll
    for (int ii = 0; ii < 8; ii++) {
        float sq = 0.f;
#pragma unroll
        for (int cc = 0; cc < 8; cc++) sq = fmaf(acc[ii][cc], acc[ii][cc], sq);
#pragma unroll
        for (int off = 16; off > 0; off >>= 1)
            sq += __shfl_xor_sync(0xffffffffu, sq, off);
        float scale = 1.0f / fmaxf(sqrtf(sq), 1e-12f);
        int row = row0 + ii * 4 + rg;
#pragma unroll
        for (int cc = 0; cc < 8; cc++)
            Out[row * D_ + cc * 32 + cg] = acc[ii][cc] * scale;
    }
}

// ---------------------------------------------------------------------------
// Kernel 2: flash-style attention with value dim 2 (coords).
//   out_new[i]  = a * (sum_j softmax_j(clip(10 q_i.k_j)) * c_j) + (1-a) c_i
//   out_disp[i] = out_new[i] - c_i
// Block: 128 threads; 32 queries (full D in SMEM) x streamed 128-key tiles.
// Thread tile: 4 queries x 8 keys, accumulated with f32x2 over d-pairs.
// tq = tid/16 (query group), tk = tid%16 (key group; 16-lane reductions).
// ---------------------------------------------------------------------------
__global__ void __launch_bounds__(128)
attn_kernel(const float* __restrict__ coords,
            const float* __restrict__ alpha_p,
            float* __restrict__ out_new,
            float* __restrict__ out_disp) {
    __shared__ __align__(16) float Q_s[32][258];   // full-width query tile
    __shared__ __align__(16) float K_s[128][18];   // 16-wide d chunk of keys
    __shared__ __align__(16) float C_s[128][2];    // key coords for the tile

    const int tid = threadIdx.x;
    const int tq  = tid >> 4;    // 0..7
    const int tk  = tid & 15;    // 0..15
    const int b   = blockIdx.y;
    const int q0  = blockIdx.x * 32;

    const float* __restrict__ Qg = g_Q + (size_t)(b * L_ + q0) * D_;
    const float* __restrict__ Kg = g_K + (size_t)b * L_ * D_;
    const float* __restrict__ Cg = coords + (size_t)b * L_ * 2;

    // Load Q tile: 32x256 floats = 2048 float4; 16 per thread.
#pragma unroll
    for (int t = 0; t < 16; t++) {
        int idx = tid + t * 128;       // float4 index, 64 per row
        int r = idx >> 6;
        int d4 = (idx & 63) * 4;
        float4 v = *(const float4*)&Qg[r * D_ + d4];
        Q_s[r][d4 + 0] = v.x; Q_s[r][d4 + 1] = v.y;
        Q_s[r][d4 + 2] = v.z; Q_s[r][d4 + 3] = v.w;
    }

    float m[4], l[4], ax[4], ay[4];
#pragma unroll
    for (int ii = 0; ii < 4; ii++) {
        m[ii] = -CUDART_INF_F; l[ii] = 0.f; ax[ii] = 0.f; ay[ii] = 0.f;
    }

    for (int t0 = 0; t0 < L_; t0 += 128) {
        unsigned long long acc2[4][8];
#pragma unroll
        for (int ii = 0; ii < 4; ii++)
#pragma unroll
            for (int jj = 0; jj < 8; jj++) acc2[ii][jj] = 0ull;

        for (int d0 = 0; d0 < D_; d0 += 16) {
            __syncthreads();   // prior reads of K_s/C_s done (also covers Q_s store ordering on 1st iter)
            // Load K chunk: 128x16 floats = 512 float4; 4 per thread.
#pragma unroll
            for (int t = 0; t < 4; t++) {
                int idx = tid + t * 128;   // float4 index, 4 per row
                int r = idx >> 2;
                int d4 = (idx & 3) * 4;
                float4 v = *(const float4*)&Kg[(size_t)(t0 + r) * D_ + d0 + d4];
                K_s[r][d4 + 0] = v.x; K_s[r][d4 + 1] = v.y;
                K_s[r][d4 + 2] = v.z; K_s[r][d4 + 3] = v.w;
            }
            if (d0 == 0) {
                *(float2*)&C_s[tid][0] = *(const float2*)&Cg[(size_t)(t0 + tid) * 2];
            }
            __syncthreads();

#pragma unroll
            for (int dp = 0; dp < 8; dp++) {
                unsigned long long q2[4], k2[8];
#pragma unroll
                for (int ii = 0; ii < 4; ii++)
                    q2[ii] = *(const unsigned long long*)&Q_s[ii * 8 + tq][d0 + 2 * dp];
#pragma unroll
                for (int jj = 0; jj < 8; jj++)
                    k2[jj] = *(const unsigned long long*)&K_s[jj * 16 + tk][2 * dp];
#pragma unroll
                for (int ii = 0; ii < 4; ii++)
#pragma unroll
                    for (int jj = 0; jj < 8; jj++)
                        acc2[ii][jj] = fma2(q2[ii], k2[jj], acc2[ii][jj]);
            }
        }

        // Key coords for this thread's 8 keys (reused across the 4 rows).
        float cx[8], cy[8];
#pragma unroll
        for (int jj = 0; jj < 8; jj++) {
            cx[jj] = C_s[jj * 16 + tk][0];
            cy[jj] = C_s[jj * 16 + tk][1];
        }

        // Online softmax update per query row.
#pragma unroll
        for (int ii = 0; ii < 4; ii++) {
            float s[8];
#pragma unroll
            for (int jj = 0; jj < 8; jj++) {
                unsigned long long v = acc2[ii][jj];
                float dot = __uint_as_float((unsigned)v) +
                            __uint_as_float((unsigned)(v >> 32));
                s[jj] = fminf(fmaxf(dot * 10.0f, -50.0f), 50.0f);
            }
            float tmax = s[0];
#pragma unroll
            for (int jj = 1; jj < 8; jj++) tmax = fmaxf(tmax, s[jj]);
#pragma unroll
            for (int off = 1; off < 16; off <<= 1)
                tmax = fmaxf(tmax, __shfl_xor_sync(0xffffffffu, tmax, off));
            float mn = fmaxf(m[ii], tmax);
            float r = __expf(m[ii] - mn);    // 0 on first tile (m = -inf)
            float pl = 0.f, px = 0.f, py = 0.f;
#pragma unroll
            for (int jj = 0; jj < 8; jj++) {
                float p = __expf(s[jj] - mn);
                pl += p;
                px = fmaf(p, cx[jj], px);
                py = fmaf(p, cy[jj], py);
            }
            m[ii]  = mn;
            l[ii]  = fmaf(l[ii], r, pl);
            ax[ii] = fmaf(ax[ii], r, px);
            ay[ii] = fmaf(ay[ii], r, py);
        }
    }

    // Final reduction across the 16 tk lanes and write out.
    float araw = alpha_p[0];
    float a = 1.0f / (1.0f + __expf(-araw));

#pragma unroll
    for (int ii = 0; ii < 4; ii++) {
        float lv = l[ii], axv = ax[ii], ayv = ay[ii];
#pragma unroll
        for (int off = 1; off < 16; off <<= 1) {
            lv  += __shfl_xor_sync(0xffffffffu, lv,  off);
            axv += __shfl_xor_sync(0xffffffffu, axv, off);
            ayv += __shfl_xor_sync(0xffffffffu, ayv, off);
        }
        if (tk == 0) {
            int row = q0 + ii * 8 + tq;
            float invl = 1.0f / lv;
            float wx = axv * invl, wy = ayv * invl;
            float2 c = *(const float2*)&Cg[(size_t)row * 2];
            float nx = a * wx + (1.0f - a) * c.x;
            float ny = a * wy + (1.0f - a) * c.y;
            size_t o = (size_t)(b * L_ + row) * 2;
            out_new[o + 0]  = nx;
            out_new[o + 1]  = ny;
            out_disp[o + 0] = nx - c.x;
            out_disp[o + 1] = ny - c.y;
        }
    }
}

// ---------------------------------------------------------------------------
// Inputs (metadata order): latents, current_coords, Wq, Wk, alpha_raw, layer_idx
// Output: concat(new_coords[B,L,2], displacement[B,L,2]) as float32.
// ---------------------------------------------------------------------------
extern "C" void kernel_launch(void* const* d_in, const int* in_sizes, int n_in,
                              void* d_out, int out_size) {
    const float* latents   = (const float*)d_in[0];
    const float* coords    = (const float*)d_in[1];
    const float* Wq        = (const float*)d_in[2];
    const float* Wk        = (const float*)d_in[3];
    const float* alpha_raw = (const float*)d_in[4];
    float* out = (float*)d_out;

    proj_norm_kernel<<<BL_ / 32, 128>>>(latents, Wq, 0);
    proj_norm_kernel<<<BL_ / 32, 128>>>(latents, Wk, 1);

    dim3 grid(L_ / 32, B_);
    attn_kernel<<<grid, 128>>>(coords, alpha_raw, out, out + BL_ * 2);
}

// round 5
// speedup vs baseline: 3.5570x; 3.5570x over previous
#include <cuda_runtime.h>
#include <math_constants.h>
#include <cstdint>

#define B_  4
#define L_  4096
#define D_  256
#define BL_ (B_ * L_)

// Scratch (allocation-free device globals), tf32-rounded values.
__device__ __align__(1024) float g_Q[BL_ * D_];        // [row][d]
__device__ __align__(1024) float g_Kt[B_ * D_ * L_];   // [b][d][key]

// ---------------------------------------------------------------------------
// helpers
// ---------------------------------------------------------------------------
__device__ __forceinline__ unsigned long long fma2(unsigned long long a,
                                                   unsigned long long b,
                                                   unsigned long long c) {
    unsigned long long d;
    asm("fma.rn.f32x2 %0, %1, %2, %3;" : "=l"(d) : "l"(a), "l"(b), "l"(c));
    return d;
}

__device__ __forceinline__ uint32_t smem_u32(const void* p) {
    uint32_t a;
    asm("{ .reg .u64 t; cvta.to.shared.u64 t, %1; cvt.u32.u64 %0, t; }"
        : "=r"(a) : "l"(p));
    return a;
}

__device__ __forceinline__ float tf32r(float x) {
    uint32_t u;
    asm("cvt.rna.tf32.f32 %0, %1;" : "=r"(u) : "f"(x));
    return __uint_as_float(u);
}

__device__ __forceinline__ float ex2f(float x) {
    float y;
    asm("ex2.approx.f32 %0, %1;" : "=f"(y) : "f"(x));
    return y;
}

__device__ __forceinline__ void cp16(uint32_t dst, const void* src) {
    asm volatile("cp.async.cg.shared.global [%0], [%1], 16;"
                 :: "r"(dst), "l"(src) : "memory");
}
__device__ __forceinline__ void cp_commit() {
    asm volatile("cp.async.commit_group;" ::: "memory");
}
__device__ __forceinline__ void cp_wait2() {
    asm volatile("cp.async.wait_group 2;" ::: "memory");
}

__device__ __forceinline__ uint32_t lds32(uint32_t a) {
    uint32_t v;
    asm volatile("ld.shared.b32 %0, [%1];" : "=r"(v) : "r"(a));
    return v;
}

#define MMA_TF32(d, a, b0, b1) \
    asm volatile("mma.sync.aligned.m16n8k8.row.col.f32.tf32.tf32.f32 " \
                 "{%0,%1,%2,%3},{%4,%5,%6,%7},{%8,%9},{%0,%1,%2,%3};" \
                 : "+f"((d)[0]), "+f"((d)[1]), "+f"((d)[2]), "+f"((d)[3]) \
                 : "r"((a)[0]), "r"((a)[1]), "r"((a)[2]), "r"((a)[3]), \
                   "r"(b0), "r"(b1))

// ---------------------------------------------------------------------------
// Kernel 1: y[r][c] = sum_d X[r][d] * W[c][d], row-L2-normalize, tf32-round.
// grid.y==0: write g_Q row-major. grid.y==1: write g_Kt transposed [d][key].
// ---------------------------------------------------------------------------
__global__ void __launch_bounds__(128)
proj_norm_kernel(const float* __restrict__ X, const float* __restrict__ Wqp,
                 const float* __restrict__ Wkp) {
    __shared__ __align__(16) float X_s[32][34];
    __shared__ __align__(16) float W_s[256][34];

    const float* __restrict__ W = blockIdx.y ? Wkp : Wqp;

    const int tid = threadIdx.x;
    const int rg  = tid >> 5;
    const int cg  = tid & 31;
    const int row0 = blockIdx.x * 32;

    unsigned long long acc2[8][8];
#pragma unroll
    for (int i = 0; i < 8; i++)
#pragma unroll
        for (int j = 0; j < 8; j++) acc2[i][j] = 0ull;

    for (int d0 = 0; d0 < D_; d0 += 32) {
#pragma unroll
        for (int t = 0; t < 2; t++) {
            int idx = tid + t * 128;
            int r = idx >> 3;
            int d4 = (idx & 7) * 4;
            float4 v = *(const float4*)&X[(row0 + r) * D_ + d0 + d4];
            X_s[r][d4 + 0] = v.x; X_s[r][d4 + 1] = v.y;
            X_s[r][d4 + 2] = v.z; X_s[r][d4 + 3] = v.w;
        }
#pragma unroll
        for (int t = 0; t < 16; t++) {
            int idx = tid + t * 128;
            int c = idx >> 3;
            int d4 = (idx & 7) * 4;
            float4 v = *(const float4*)&W[c * D_ + d0 + d4];
            W_s[c][d4 + 0] = v.x; W_s[c][d4 + 1] = v.y;
            W_s[c][d4 + 2] = v.z; W_s[c][d4 + 3] = v.w;
        }
        __syncthreads();
#pragma unroll 4
        for (int d = 0; d < 32; d += 2) {
            unsigned long long w2[8], x2[8];
#pragma unroll
            for (int cc = 0; cc < 8; cc++)
                w2[cc] = *(const unsigned long long*)&W_s[cc * 32 + cg][d];
#pragma unroll
            for (int ii = 0; ii < 8; ii++)
                x2[ii] = *(const unsigned long long*)&X_s[ii * 4 + rg][d];
#pragma unroll
            for (int ii = 0; ii < 8; ii++)
#pragma unroll
                for (int cc = 0; cc < 8; cc++)
                    acc2[ii][cc] = fma2(x2[ii], w2[cc], acc2[ii][cc]);
        }
        __syncthreads();
    }

    // T overlay for the K-transpose path (W_s is dead now). Stride 33.
    float* T = &W_s[0][0];

#pragma unroll
    for (int ii = 0; ii < 8; ii++) {
        float dot[8];
        float sq = 0.f;
#pragma unroll
        for (int cc = 0; cc < 8; cc++) {
            unsigned long long v = acc2[ii][cc];
            dot[cc] = __uint_as_float((unsigned)v) +
                      __uint_as_float((unsigned)(v >> 32));
            sq = fmaf(dot[cc], dot[cc], sq);
        }
#pragma unroll
        for (int off = 16; off > 0; off >>= 1)
            sq += __shfl_xor_sync(0xffffffffu, sq, off);
        float scale = 1.0f / fmaxf(sqrtf(sq), 1e-12f);
        int rowl = ii * 4 + rg;
        if (blockIdx.y == 0) {
            int row = row0 + rowl;
#pragma unroll
            for (int cc = 0; cc < 8; cc++)
                g_Q[row * D_ + cc * 32 + cg] = tf32r(dot[cc] * scale);
        } else {
#pragma unroll
            for (int cc = 0; cc < 8; cc++)
                T[(cc * 32 + cg) * 33 + rowl] = tf32r(dot[cc] * scale);
        }
    }

    if (blockIdx.y == 1) {
        __syncthreads();
        int bb = row0 >> 12;          // batch
        int l0 = row0 & 4095;         // key offset within batch
        float* base = g_Kt + ((size_t)bb * D_) * L_ + l0;
#pragma unroll
        for (int it = 0; it < 64; it++) {
            int idx = tid + it * 128;       // 0..8191
            int d = idx >> 5, key = idx & 31;
            base[(size_t)d * L_ + key] = T[d * 33 + key];
        }
    }
}

// ---------------------------------------------------------------------------
// Kernel 2: flash attention via mma.sync tf32.
// CTA: 128 q x all keys; 256 threads = 8 warps (warpm 0..3, warpn 0..1).
// Warp tile 32(m) x 64(n); K streamed in 32-d x 128-key chunks (cp.async ring 4).
// Scores ~N(0, 0.625) (unit q,k, temp 10) -> clip is a no-op, no running max.
// ---------------------------------------------------------------------------
#define QSTRIDE 260
#define KSTRIDE 136
#define SLOT_B  (32 * KSTRIDE * 4)          /* 17408 */
#define SM_Q    0
#define SM_K    133120                      /* 128*260*4 */
#define SM_C    (SM_K + 4 * SLOT_B)         /* 202752 */
#define SM_R    (SM_C + 1024)               /* 203776 */
#define SM_TOT  (SM_R + 4096)               /* 207872 */

#define SCALE_EX2 14.4269504088896340f      /* 10 * log2(e) */

__global__ void __launch_bounds__(256, 1)
attn_kernel(const float* __restrict__ coords,
            const float* __restrict__ alpha_p,
            float* __restrict__ out_new,
            float* __restrict__ out_disp) {
    extern __shared__ __align__(1024) char smem[];
    const uint32_t sb = smem_u32(smem);
    const int tid  = threadIdx.x;
    const int lane = tid & 31;
    const int warp = tid >> 5;
    const int warpm = warp & 3, warpn = warp >> 2;
    const int g  = lane >> 2, t4 = lane & 3;
    const int b  = blockIdx.y;
    const int q0 = blockIdx.x * 128;

    const float* __restrict__ Qg  = g_Q + (size_t)(b * L_ + q0) * D_;
    const float* __restrict__ Ktg = g_Kt + (size_t)b * D_ * L_;
    const float2* __restrict__ Cg2 = (const float2*)coords + (size_t)b * L_;

    // ---- prologue: Q tile + first 3 K chunks via cp.async ----
#pragma unroll
    for (int i = 0; i < 32; i++) {
        int seg = tid + 256 * i;            // 0..8191
        int row = seg >> 6, o = seg & 63;   // 64 x 16B per row
        cp16(sb + SM_Q + row * (QSTRIDE * 4) + o * 16, Qg + row * D_ + o * 4);
    }
    cp_commit();
#pragma unroll
    for (int gc = 0; gc < 3; gc++) {
        int t0 = (gc >> 3) * 128, d0 = (gc & 7) * 32;
        uint32_t slot = sb + SM_K + (gc & 3) * SLOT_B;
        const float* src = Ktg + (size_t)d0 * L_ + t0;
#pragma unroll
        for (int i = 0; i < 4; i++) {
            int seg = tid + 256 * i;
            int dr = seg >> 5, ko = (seg & 31) * 4;
            cp16(slot + dr * (KSTRIDE * 4) + ko * 4, src + (size_t)dr * L_ + ko);
        }
        cp_commit();
    }

    float l[4], ax[4], ay[4];
#pragma unroll
    for (int s = 0; s < 4; s++) { l[s] = 0.f; ax[s] = 0.f; ay[s] = 0.f; }

    for (int t = 0; t < 32; t++) {
        __syncthreads();                    // prev tile epilogue done w/ C_s
        if (tid < 128)
            ((float2*)(smem + SM_C))[tid] = Cg2[t * 128 + tid];

        float S[2][8][4];
#pragma unroll
        for (int mt = 0; mt < 2; mt++)
#pragma unroll
            for (int nb = 0; nb < 8; nb++)
#pragma unroll
                for (int r = 0; r < 4; r++) S[mt][nb][r] = 0.f;

        for (int c8 = 0; c8 < 8; c8++) {
            const int gc = t * 8 + c8;
            cp_wait2();
            __syncthreads();
            // prefetch chunk gc+3 into slot (gc+3)&3 (== (gc-1)&3, now free)
            if (gc + 3 < 256) {
                int nc = gc + 3;
                int t0 = (nc >> 3) * 128, d0 = (nc & 7) * 32;
                uint32_t slot = sb + SM_K + (nc & 3) * SLOT_B;
                const float* src = Ktg + (size_t)d0 * L_ + t0;
#pragma unroll
                for (int i = 0; i < 4; i++) {
                    int seg = tid + 256 * i;
                    int dr = seg >> 5, ko = (seg & 31) * 4;
                    cp16(slot + dr * (KSTRIDE * 4) + ko * 4,
                         src + (size_t)dr * L_ + ko);
                }
            }
            cp_commit();

            const uint32_t slot = sb + SM_K + (gc & 3) * SLOT_B;
#pragma unroll
            for (int ds = 0; ds < 4; ds++) {
                uint32_t a[2][4];
                const int colb = (c8 * 32 + ds * 8 + t4) * 4;
#pragma unroll
                for (int mt = 0; mt < 2; mt++) {
                    uint32_t qb = sb + SM_Q +
                        (warpm * 32 + mt * 16 + g) * (QSTRIDE * 4) + colb;
                    a[mt][0] = lds32(qb);
                    a[mt][1] = lds32(qb + 8 * QSTRIDE * 4);
                    a[mt][2] = lds32(qb + 16);
                    a[mt][3] = lds32(qb + 8 * QSTRIDE * 4 + 16);
                }
                uint32_t kb = slot + (ds * 8 + t4) * (KSTRIDE * 4) +
                              (warpn * 64 + g) * 4;
#pragma unroll
                for (int nb = 0; nb < 8; nb++) {
                    uint32_t b0 = lds32(kb + nb * 32);
                    uint32_t b1 = lds32(kb + nb * 32 + 4 * KSTRIDE * 4);
                    MMA_TF32(S[0][nb], a[0], b0, b1);
                    MMA_TF32(S[1][nb], a[1], b0, b1);
                }
            }
        }

        // ---- epilogue: p = 2^(s*10*log2e); accumulate l, ax, ay ----
        // c0/c1 of mma tile (m-row g) sit at key cols warpn*64 + nb*8 + 2*t4 (+1);
        // as float4 over float2-coords: index warpn*32 + nb*4 + t4.
        const float4* __restrict__ C4 = (const float4*)(smem + SM_C);
#pragma unroll
        for (int mt = 0; mt < 2; mt++) {
            const int s0 = mt * 2, s1 = mt * 2 + 1;
#pragma unroll
            for (int nb = 0; nb < 8; nb++) {
                float4 cc = C4[warpn * 32 + nb * 4 + t4];
                float p0 = ex2f(S[mt][nb][0] * SCALE_EX2);
                float p1 = ex2f(S[mt][nb][1] * SCALE_EX2);
                float p2 = ex2f(S[mt][nb][2] * SCALE_EX2);
                float p3 = ex2f(S[mt][nb][3] * SCALE_EX2);
                l[s0] += p0 + p1;
                ax[s0] = fmaf(p0, cc.x, ax[s0]); ay[s0] = fmaf(p0, cc.y, ay[s0]);
                ax[s0] = fmaf(p1, cc.z, ax[s0]); ay[s0] = fmaf(p1, cc.w, ay[s0]);
                l[s1] += p2 + p3;
                ax[s1] = fmaf(p2, cc.x, ax[s1]); ay[s1] = fmaf(p2, cc.y, ay[s1]);
                ax[s1] = fmaf(p3, cc.z, ax[s1]); ay[s1] = fmaf(p3, cc.w, ay[s1]);
            }
        }
    }

    // ---- cross-lane + cross-warpn reduction, then output ----
    float4* __restrict__ red = (float4*)(smem + SM_R);
#pragma unroll
    for (int s = 0; s < 4; s++) {
#pragma unroll
        for (int off = 1; off < 4; off <<= 1) {
            l[s]  += __shfl_xor_sync(0xffffffffu, l[s],  off);
            ax[s] += __shfl_xor_sync(0xffffffffu, ax[s], off);
            ay[s] += __shfl_xor_sync(0xffffffffu, ay[s], off);
        }
        if (t4 == 0) {
            int rowl = warpm * 32 + (s >> 1) * 16 + (s & 1) * 8 + g;
            red[warpn * 128 + rowl] = make_float4(l[s], ax[s], ay[s], 0.f);
        }
    }
    __syncthreads();

    if (tid < 128) {
        float4 r0 = red[tid], r1 = red[128 + tid];
        float lv  = r0.x + r1.x;
        float axv = r0.y + r1.y;
        float ayv = r0.z + r1.z;
        float a = 1.0f / (1.0f + __expf(-alpha_p[0]));
        float inv = 1.0f / lv;
        float wx = axv * inv, wy = ayv * inv;
        float2 c = Cg2[q0 + tid];
        float nx = a * wx + (1.0f - a) * c.x;
        float ny = a * wy + (1.0f - a) * c.y;
        size_t o = ((size_t)b * L_ + q0 + tid) * 2;
        out_new[o + 0]  = nx;
        out_new[o + 1]  = ny;
        out_disp[o + 0] = nx - c.x;
        out_disp[o + 1] = ny - c.y;
    }
}

// ---------------------------------------------------------------------------
// Inputs: latents, current_coords, Wq, Wk, alpha_raw, layer_idx.
// Output: concat(new_coords[B,L,2], displacement[B,L,2]) fp32.
// ---------------------------------------------------------------------------
extern "C" void kernel_launch(void* const* d_in, const int* in_sizes, int n_in,
                              void* d_out, int out_size) {
    const float* latents   = (const float*)d_in[0];
    const float* coords    = (const float*)d_in[1];
    const float* Wq        = (const float*)d_in[2];
    const float* Wk        = (const float*)d_in[3];
    const float* alpha_raw = (const float*)d_in[4];
    float* out = (float*)d_out;

    proj_norm_kernel<<<dim3(BL_ / 32, 2), 128>>>(latents, Wq, Wk);

    cudaFuncSetAttribute(attn_kernel,
                         cudaFuncAttributeMaxDynamicSharedMemorySize, SM_TOT);
    attn_kernel<<<dim3(L_ / 128, B_), 256, SM_TOT>>>(
        coords, alpha_raw, out, out + BL_ * 2);
}